// round 11
// baseline (speedup 1.0000x reference)
#include <cuda_runtime.h>
#include <cuda_bf16.h>
#include <stdint.h>

#define NROW 4096
#define DIM  1024
#define NTL  512         // row_loss threads
#define RS   40          // padded smem row stride (bf16 elems) for conflict-free ldmatrix

// Static device scratch (no runtime allocation allowed).
__device__ __nv_bfloat16 g_Xb[(size_t)NROW * DIM];   // 8 MB normalized embeddings (bf16)
__device__ float g_SIM[(size_t)NROW * NROW];         // 64 MB similarity matrix
__device__ unsigned char g_cls[NROW];
__device__ float g_rowloss[NROW];

// Monotone fp32 <-> uint32 key (ascending order preserved)
__device__ __forceinline__ unsigned int f2k(float f) {
    unsigned int u = __float_as_uint(f);
    return (u & 0x80000000u) ? ~u : (u | 0x80000000u);
}
__device__ __forceinline__ float k2f(unsigned int k) {
    unsigned int u = (k & 0x80000000u) ? (k & 0x7FFFFFFFu) : ~k;
    return __uint_as_float(u);
}

// ---------------------------------------------------------------------------
// Classes: reference declares int64 targets, but JAX without x64 emits int32.
__global__ __launch_bounds__(1024) void cls_kernel(const int* __restrict__ tgt32) {
    __shared__ int s_any;
    const int t = threadIdx.x;
    if (t == 0) s_any = 0;
    __syncthreads();
    int any = 0;
    for (int j = t; j < NROW / 2; j += 1024)
        any |= (tgt32[2 * j + 1] != 0);
    if (any) atomicOr(&s_any, 1);
    __syncthreads();
    const bool is64 = (s_any == 0);
    for (int i = t; i < NROW; i += 1024)
        g_cls[i] = (unsigned char)(is64 ? tgt32[2 * i] : tgt32[i]);
}

// ---------------------------------------------------------------------------
// Single-pass normalize: each thread owns one float4 of the row.
__global__ __launch_bounds__(256) void normalize_kernel(const float* __restrict__ emb) {
    const int i = blockIdx.x;
    const int t = threadIdx.x;
    const int lane = t & 31;
    const int wid  = t >> 5;
    __shared__ float s[8];

    float4 v = *(const float4*)(emb + (size_t)i * DIM + t * 4);
    float ss = v.x * v.x + v.y * v.y + v.z * v.z + v.w * v.w;
#pragma unroll
    for (int o = 16; o > 0; o >>= 1) ss += __shfl_xor_sync(0xFFFFFFFFu, ss, o);
    if (lane == 0) s[wid] = ss;
    __syncthreads();
    float tot = 0.f;
#pragma unroll
    for (int w = 0; w < 8; w++) tot += s[w];
    const float norm = fmaxf(sqrtf(tot), 1e-12f);

    unsigned int u0 = (unsigned int)__bfloat16_as_ushort(__float2bfloat16(v.x / norm));
    unsigned int u1 = (unsigned int)__bfloat16_as_ushort(__float2bfloat16(v.y / norm));
    unsigned int u2 = (unsigned int)__bfloat16_as_ushort(__float2bfloat16(v.z / norm));
    unsigned int u3 = (unsigned int)__bfloat16_as_ushort(__float2bfloat16(v.w / norm));
    uint2 pk;
    pk.x = u0 | (u1 << 16);
    pk.y = u2 | (u3 << 16);
    *(uint2*)(g_Xb + (size_t)i * DIM + t * 4) = pk;
}

// ---------------------------------------------------------------------------
// SIM = X * X^T in bf16 tensor cores (R8-proven). SYMMETRIC: 528 lower-
// triangular 128x128 tiles; off-diagonal tiles also store their transpose,
// staged via smem so all global stores stay coalesced.
__device__ __forceinline__ void cp16(unsigned int smem_dst, const void* gsrc) {
    asm volatile("cp.async.cg.shared.global [%0], [%1], 16;\n" :: "r"(smem_dst), "l"(gsrc));
}
__device__ __forceinline__ void cp_commit() { asm volatile("cp.async.commit_group;\n"); }
__device__ __forceinline__ void cp_wait0() { asm volatile("cp.async.wait_group 0;\n"); }

__global__ __launch_bounds__(256) void gemm_kernel() {
    __shared__ __align__(16) char smbuf[2 * 128 * RS * 2 * 2];
    typedef __nv_bfloat16 Tile[128][RS];
    Tile* sA = reinterpret_cast<Tile*>(smbuf);
    Tile* sB = reinterpret_cast<Tile*>(smbuf + 2 * 128 * RS * 2);
    float (*tr)[132] = reinterpret_cast<float (*)[132]>(smbuf);

    const int t    = threadIdx.x;
    const int lane = t & 31;
    const int wid  = t >> 5;
    const int wm   = (wid >> 2) * 64;
    const int wn   = (wid & 3) * 32;

    const int b = blockIdx.x;
    int p = (int)((sqrtf(8.f * (float)b + 1.f) - 1.f) * 0.5f);
    while ((p + 1) * (p + 2) / 2 <= b) p++;
    while (p * (p + 1) / 2 > b) p--;
    const int q  = b - p * (p + 1) / 2;
    const int bi = p * 128;
    const int bj = q * 128;

    float acc[4][4][4];
#pragma unroll
    for (int mt = 0; mt < 4; mt++)
#pragma unroll
        for (int nt = 0; nt < 4; nt++)
#pragma unroll
            for (int r = 0; r < 4; r++) acc[mt][nt][r] = 0.f;

    auto load_stage = [&](int buf, int k0) {
#pragma unroll
        for (int c = t; c < 512; c += 256) {
            int row = c >> 2, off = (c & 3) * 8;
            cp16((unsigned int)__cvta_generic_to_shared(&sA[buf][row][off]),
                 g_Xb + (size_t)(bi + row) * DIM + k0 + off);
            cp16((unsigned int)__cvta_generic_to_shared(&sB[buf][row][off]),
                 g_Xb + (size_t)(bj + row) * DIM + k0 + off);
        }
    };

    load_stage(0, 0);
    cp_commit();
    cp_wait0();
    __syncthreads();

    for (int s = 0; s < DIM / 32; s++) {
        const int cbuf = s & 1;
        if (s + 1 < DIM / 32) {
            load_stage((s + 1) & 1, (s + 1) * 32);
            cp_commit();
        }
#pragma unroll
        for (int ks = 0; ks < 2; ks++) {
            unsigned int a[4][4], bb[4][2];
#pragma unroll
            for (int mt = 0; mt < 4; mt++) {
                unsigned int addr = (unsigned int)__cvta_generic_to_shared(
                    &sA[cbuf][wm + mt * 16 + (lane & 15)][ks * 16 + (lane >> 4) * 8]);
                asm volatile("ldmatrix.sync.aligned.m8n8.x4.shared.b16 {%0,%1,%2,%3}, [%4];"
                             : "=r"(a[mt][0]), "=r"(a[mt][1]), "=r"(a[mt][2]), "=r"(a[mt][3])
                             : "r"(addr));
            }
#pragma unroll
            for (int nt = 0; nt < 4; nt++) {
                unsigned int addr = (unsigned int)__cvta_generic_to_shared(
                    &sB[cbuf][wn + nt * 8 + (lane & 7)][ks * 16 + ((lane >> 3) & 1) * 8]);
                asm volatile("ldmatrix.sync.aligned.m8n8.x2.shared.b16 {%0,%1}, [%2];"
                             : "=r"(bb[nt][0]), "=r"(bb[nt][1]) : "r"(addr));
            }
#pragma unroll
            for (int mt = 0; mt < 4; mt++)
#pragma unroll
                for (int nt = 0; nt < 4; nt++) {
                    asm volatile(
                        "mma.sync.aligned.m16n8k16.row.col.f32.bf16.bf16.f32 "
                        "{%0,%1,%2,%3},{%4,%5,%6,%7},{%8,%9},{%0,%1,%2,%3};"
                        : "+f"(acc[mt][nt][0]), "+f"(acc[mt][nt][1]),
                          "+f"(acc[mt][nt][2]), "+f"(acc[mt][nt][3])
                        : "r"(a[mt][0]), "r"(a[mt][1]), "r"(a[mt][2]), "r"(a[mt][3]),
                          "r"(bb[nt][0]), "r"(bb[nt][1]));
                }
        }
        if (s + 1 < DIM / 32) cp_wait0();
        __syncthreads();
    }

#pragma unroll
    for (int mt = 0; mt < 4; mt++) {
#pragma unroll
        for (int nt = 0; nt < 4; nt++) {
            int r0 = bi + wm + mt * 16 + (lane >> 2);
            int c0 = bj + wn + nt * 8 + (lane & 3) * 2;
            *(float2*)(g_SIM + (size_t)r0 * NROW + c0) =
                make_float2(acc[mt][nt][0], acc[mt][nt][1]);
            *(float2*)(g_SIM + (size_t)(r0 + 8) * NROW + c0) =
                make_float2(acc[mt][nt][2], acc[mt][nt][3]);
        }
    }

    if (p != q) {
        for (int cc = 0; cc < 4; cc++) {
            __syncthreads();
            if ((wid & 3) == cc) {
#pragma unroll
                for (int mt = 0; mt < 4; mt++)
#pragma unroll
                    for (int nt = 0; nt < 4; nt++) {
                        int r0 = wm + mt * 16 + (lane >> 2);
                        int c0 = nt * 8 + (lane & 3) * 2;
                        tr[c0    ][r0    ] = acc[mt][nt][0];
                        tr[c0 + 1][r0    ] = acc[mt][nt][1];
                        tr[c0    ][r0 + 8] = acc[mt][nt][2];
                        tr[c0 + 1][r0 + 8] = acc[mt][nt][3];
                    }
            }
            __syncthreads();
            const int c = t >> 3;
            const int r = (t & 7) * 16;
            float* dst = g_SIM + (size_t)(bj + cc * 32 + c) * NROW + bi + r;
#pragma unroll
            for (int k = 0; k < 4; k++)
                *(float4*)(dst + k * 4) = *(float4*)(&tr[c][r + k * 4]);
        }
    }
}

// ---------------------------------------------------------------------------
// Per-row loss, 512 threads (2 elements x float4 per thread). Same algorithm
// as the R6-proven version; threads >= 256 act as zero-count phantom bins in
// the bucket-select suffix scans.
__global__ __launch_bounds__(NTL) void row_loss_kernel() {
    __shared__ unsigned int s_k[NROW];      // 16 KB
    __shared__ float        s_p[NROW];      // 16 KB
    __shared__ unsigned int s_hist[256];
    __shared__ unsigned int s_cand[256];
    __shared__ unsigned int s_wtot[16];
    __shared__ float        s_red[16];
    __shared__ unsigned int sh_sel, sh_r, sh_h, sh_cnt;
    __shared__ unsigned int sh_key, sh_m;

    const int i    = blockIdx.x;
    const int t    = threadIdx.x;
    const int lane = t & 31;
    const int wid  = t >> 5;          // 0..15
    const unsigned char myc = g_cls[i];
    const float* row = g_SIM + (size_t)i * NROW;

    if (t < 256) s_hist[t] = 0;
    __syncthreads();

    // ---- load pass: fill s_k/s_p, round-0 histogram, K count, pos_max ----
    float pmax = -1e30f;
    int   kneg = 0;
#pragma unroll
    for (int c = 0; c < 2; c++) {
        const int j0 = (c * NTL + t) * 4;
        float4 v4 = *(const float4*)(row + j0);
        uchar4 c4 = *(const uchar4*)(g_cls + j0);
        float vv[4] = {v4.x, v4.y, v4.z, v4.w};
        unsigned char cc[4] = {c4.x, c4.y, c4.z, c4.w};
        unsigned int kk[4];
        float        pp[4];
#pragma unroll
        for (int e = 0; e < 4; e++) {
            const int idx = j0 + e;
            if (cc[e] != myc) {
                const unsigned int key = f2k(vv[e]);
                kk[e] = key; pp[e] = -1e30f;
                kneg++;
                atomicAdd(&s_hist[key >> 24], 1u);
            } else {
                kk[e] = 0u;
                pp[e] = (idx != i) ? vv[e] : -1e30f;
                pmax = fmaxf(pmax, pp[e]);
            }
        }
        *(uint4*)(s_k + j0)  = make_uint4(kk[0], kk[1], kk[2], kk[3]);
        *(float4*)(s_p + j0) = make_float4(pp[0], pp[1], pp[2], pp[3]);
    }
#pragma unroll
    for (int o = 16; o > 0; o >>= 1) {
        kneg += __shfl_xor_sync(0xFFFFFFFFu, kneg, o);
        pmax  = fmaxf(pmax, __shfl_xor_sync(0xFFFFFFFFu, pmax, o));
    }
    if (lane == 0) { s_wtot[wid] = (unsigned int)kneg; s_red[wid] = pmax; }
    __syncthreads();
    unsigned int K = 0; float pm = -1e30f;
#pragma unroll
    for (int w = 0; w < 16; w++) { K += s_wtot[w]; pm = fmaxf(pm, s_red[w]); }
    const int drop = max((int)floorf((float)K * 0.05f), 1);
    unsigned int r = (unsigned int)(drop + 1);

    // bucket select over 256 bins; threads >= 256 are zero-count phantoms
    auto select_bucket = [&](unsigned int rr) {
        const unsigned int h = (t < 256) ? s_hist[t] : 0u;
        unsigned int suf = h;
#pragma unroll
        for (int o = 1; o < 32; o <<= 1) {
            const unsigned int w = __shfl_down_sync(0xFFFFFFFFu, suf, o);
            if (lane + o < 32) suf += w;
        }
        if (lane == 0) s_wtot[wid] = suf;
        __syncthreads();
#pragma unroll
        for (int w = 0; w < 16; w++) if (w > wid) suf += s_wtot[w];
        if (suf >= rr && (suf - h) < rr) {       // requires h > 0 -> t < 256
            sh_sel = (unsigned int)t;
            sh_r   = rr - (suf - h);
            sh_h   = h;
        }
        __syncthreads();
    };

    // ---- round 0 (hist already built) ----
    select_bucket(r);
    unsigned int prefix = sh_sel;
    r = sh_r;
    __syncthreads();

    // ---- round 1 ----
    if (t < 256) s_hist[t] = 0;
    __syncthreads();
#pragma unroll
    for (int c = 0; c < 2; c++) {
        uint4 k4 = *(const uint4*)(s_k + (c * NTL + t) * 4);
        unsigned int kk[4] = {k4.x, k4.y, k4.z, k4.w};
#pragma unroll
        for (int e = 0; e < 4; e++)
            if ((kk[e] >> 24) == prefix)
                atomicAdd(&s_hist[(kk[e] >> 16) & 255u], 1u);
    }
    __syncthreads();
    select_bucket(r);
    prefix = (prefix << 8) | sh_sel;
    r = sh_r;
    __syncthreads();

    // ---- candidate collection for low 16 bits ----
    if (t == 0) sh_cnt = 0;
    __syncthreads();
#pragma unroll
    for (int c = 0; c < 2; c++) {
        uint4 k4 = *(const uint4*)(s_k + (c * NTL + t) * 4);
        unsigned int kk[4] = {k4.x, k4.y, k4.z, k4.w};
#pragma unroll
        for (int e = 0; e < 4; e++)
            if ((kk[e] >> 16) == prefix) {
                unsigned int pslot = atomicAdd(&sh_cnt, 1u);
                if (pslot < 256) s_cand[pslot] = kk[e];
            }
    }
    __syncthreads();

    if (sh_cnt <= 256u) {
        const unsigned int C = sh_cnt;
        if (t < (int)C) {
            const unsigned int k = s_cand[t];
            unsigned int cg = 0, ce = 0;
            for (unsigned int j = 0; j < C; j++) {
                const unsigned int kj = s_cand[j];
                cg += (kj > k); ce += (kj == k);
            }
            if (cg < r && r <= cg + ce) {
                sh_key = k;
                sh_m   = ce + 1u - (r - cg);
            }
        }
        __syncthreads();
    } else {
        // exact fallback: full radix rounds 2 and 3
#pragma unroll
        for (int shift = 8; shift >= 0; shift -= 8) {
            if (t < 256) s_hist[t] = 0;
            __syncthreads();
#pragma unroll
            for (int c = 0; c < 2; c++) {
                uint4 k4 = *(const uint4*)(s_k + (c * NTL + t) * 4);
                unsigned int kk[4] = {k4.x, k4.y, k4.z, k4.w};
#pragma unroll
                for (int e = 0; e < 4; e++)
                    if ((kk[e] >> (shift + 8)) == prefix)
                        atomicAdd(&s_hist[(kk[e] >> shift) & 255u], 1u);
            }
            __syncthreads();
            select_bucket(r);
            prefix = (prefix << 8) | sh_sel;
            r = sh_r;
            if (t == 0 && shift == 0) { sh_key = prefix; sh_m = sh_h + 1u - sh_r; }
            __syncthreads();
        }
    }

    const float T = k2f(sh_key);
    const int   m = (int)sh_m;

    // ---- fused final pass: pos_loss + neg_sum ----
    const float thr   = T + 0.1f;
    const float lower = fmaxf(0.6f, pm) - 0.1f;
    float ploss = 0.f, ns = 0.f;
#pragma unroll
    for (int c = 0; c < 2; c++) {
        const int j0 = (c * NTL + t) * 4;
        uint4  k4 = *(const uint4*)(s_k + j0);
        float4 p4 = *(const float4*)(s_p + j0);
        unsigned int kk[4] = {k4.x, k4.y, k4.z, k4.w};
        float        pp[4] = {p4.x, p4.y, p4.z, p4.w};
#pragma unroll
        for (int e = 0; e < 4; e++) {
            if (kk[e]) {
                const float v = k2f(kk[e]);
                if (v < T && v > lower) ns += v;
            }
            if (pp[e] > -1e29f && pp[e] < thr) ploss += 1.0f - pp[e];
        }
    }
#pragma unroll
    for (int o = 16; o > 0; o >>= 1) {
        ploss += __shfl_xor_sync(0xFFFFFFFFu, ploss, o);
        ns    += __shfl_xor_sync(0xFFFFFFFFu, ns, o);
    }
    if (lane == 0) { s_red[wid] = ploss; s_wtot[wid] = __float_as_uint(ns); }
    __syncthreads();

    if (t == 0) {
        float pl = 0.f, nss = 0.f;
#pragma unroll
        for (int w = 0; w < 16; w++) { pl += s_red[w]; nss += __uint_as_float(s_wtot[w]); }
        float loss = 0.f;
        if (pm > -1e29f) {
            loss = pl + nss;
            if (T > lower) loss += (float)m * T;
        }
        g_rowloss[i] = loss;
    }
}

// ---------------------------------------------------------------------------
__global__ void finalize_kernel(float* __restrict__ out) {
    __shared__ float s[1024];
    int t = threadIdx.x;
    float a = 0.f;
    for (int j = t; j < NROW; j += 1024) a += g_rowloss[j];
    s[t] = a; __syncthreads();
    for (int o = 512; o > 0; o >>= 1) { if (t < o) s[t] += s[t + o]; __syncthreads(); }
    if (t == 0) out[0] = s[0] / (float)NROW;
}

// ---------------------------------------------------------------------------
extern "C" void kernel_launch(void* const* d_in, const int* in_sizes, int n_in,
                              void* d_out, int out_size) {
    const float* emb   = (const float*)d_in[0];
    const int*   tgt32 = (const int*)d_in[1];
    float* out = (float*)d_out;

    cls_kernel<<<1, 1024>>>(tgt32);
    normalize_kernel<<<NROW, 256>>>(emb);
    gemm_kernel<<<528, 256>>>();
    row_loss_kernel<<<NROW, NTL>>>();
    finalize_kernel<<<1, 1024>>>(out);
}

// round 12
// speedup vs baseline: 1.0871x; 1.0871x over previous
#include <cuda_runtime.h>
#include <cuda_bf16.h>
#include <stdint.h>

#define NROW 4096
#define DIM  1024
#define NT   256
#define RS   40          // padded smem row stride (bf16 elems) for conflict-free ldmatrix

// Static device scratch (no runtime allocation allowed).
__device__ __nv_bfloat16 g_Xb[(size_t)NROW * DIM];   // 8 MB normalized embeddings (bf16)
__device__ float g_SIM[(size_t)NROW * NROW];         // 64 MB similarity matrix
__device__ unsigned char g_cls[NROW];
__device__ float g_rowloss[NROW];

// Monotone fp32 <-> uint32 key (ascending order preserved)
__device__ __forceinline__ unsigned int f2k(float f) {
    unsigned int u = __float_as_uint(f);
    return (u & 0x80000000u) ? ~u : (u | 0x80000000u);
}
__device__ __forceinline__ float k2f(unsigned int k) {
    unsigned int u = (k & 0x80000000u) ? (k & 0x7FFFFFFFu) : ~k;
    return __uint_as_float(u);
}

// ---------------------------------------------------------------------------
// Classes: reference declares int64 targets, but JAX without x64 emits int32.
__global__ __launch_bounds__(1024) void cls_kernel(const int* __restrict__ tgt32) {
    __shared__ int s_any;
    const int t = threadIdx.x;
    if (t == 0) s_any = 0;
    __syncthreads();
    int any = 0;
    for (int j = t; j < NROW / 2; j += 1024)
        any |= (tgt32[2 * j + 1] != 0);
    if (any) atomicOr(&s_any, 1);
    __syncthreads();
    const bool is64 = (s_any == 0);
    for (int i = t; i < NROW; i += 1024)
        g_cls[i] = (unsigned char)(is64 ? tgt32[2 * i] : tgt32[i]);
}

// ---------------------------------------------------------------------------
// Single-pass normalize: each thread owns one float4 of the row.
__global__ __launch_bounds__(256) void normalize_kernel(const float* __restrict__ emb) {
    const int i = blockIdx.x;
    const int t = threadIdx.x;
    const int lane = t & 31;
    const int wid  = t >> 5;
    __shared__ float s[8];

    float4 v = *(const float4*)(emb + (size_t)i * DIM + t * 4);
    float ss = v.x * v.x + v.y * v.y + v.z * v.z + v.w * v.w;
#pragma unroll
    for (int o = 16; o > 0; o >>= 1) ss += __shfl_xor_sync(0xFFFFFFFFu, ss, o);
    if (lane == 0) s[wid] = ss;
    __syncthreads();
    float tot = 0.f;
#pragma unroll
    for (int w = 0; w < 8; w++) tot += s[w];
    const float norm = fmaxf(sqrtf(tot), 1e-12f);

    unsigned int u0 = (unsigned int)__bfloat16_as_ushort(__float2bfloat16(v.x / norm));
    unsigned int u1 = (unsigned int)__bfloat16_as_ushort(__float2bfloat16(v.y / norm));
    unsigned int u2 = (unsigned int)__bfloat16_as_ushort(__float2bfloat16(v.z / norm));
    unsigned int u3 = (unsigned int)__bfloat16_as_ushort(__float2bfloat16(v.w / norm));
    uint2 pk;
    pk.x = u0 | (u1 << 16);
    pk.y = u2 | (u3 << 16);
    *(uint2*)(g_Xb + (size_t)i * DIM + t * 4) = pk;
}

// ---------------------------------------------------------------------------
// SIM = X * X^T in bf16 tensor cores (R8-proven). SYMMETRIC: 528 lower-
// triangular 128x128 tiles; off-diagonal tiles also store their transpose,
// staged via smem so all global stores stay coalesced.
__device__ __forceinline__ void cp16(unsigned int smem_dst, const void* gsrc) {
    asm volatile("cp.async.cg.shared.global [%0], [%1], 16;\n" :: "r"(smem_dst), "l"(gsrc));
}
__device__ __forceinline__ void cp_commit() { asm volatile("cp.async.commit_group;\n"); }
__device__ __forceinline__ void cp_wait0() { asm volatile("cp.async.wait_group 0;\n"); }

__global__ __launch_bounds__(256) void gemm_kernel() {
    __shared__ __align__(16) char smbuf[2 * 128 * RS * 2 * 2];
    typedef __nv_bfloat16 Tile[128][RS];
    Tile* sA = reinterpret_cast<Tile*>(smbuf);
    Tile* sB = reinterpret_cast<Tile*>(smbuf + 2 * 128 * RS * 2);
    float (*tr)[132] = reinterpret_cast<float (*)[132]>(smbuf);

    const int t    = threadIdx.x;
    const int lane = t & 31;
    const int wid  = t >> 5;
    const int wm   = (wid >> 2) * 64;
    const int wn   = (wid & 3) * 32;

    const int b = blockIdx.x;
    int p = (int)((sqrtf(8.f * (float)b + 1.f) - 1.f) * 0.5f);
    while ((p + 1) * (p + 2) / 2 <= b) p++;
    while (p * (p + 1) / 2 > b) p--;
    const int q  = b - p * (p + 1) / 2;
    const int bi = p * 128;
    const int bj = q * 128;

    float acc[4][4][4];
#pragma unroll
    for (int mt = 0; mt < 4; mt++)
#pragma unroll
        for (int nt = 0; nt < 4; nt++)
#pragma unroll
            for (int r = 0; r < 4; r++) acc[mt][nt][r] = 0.f;

    auto load_stage = [&](int buf, int k0) {
#pragma unroll
        for (int c = t; c < 512; c += 256) {
            int row = c >> 2, off = (c & 3) * 8;
            cp16((unsigned int)__cvta_generic_to_shared(&sA[buf][row][off]),
                 g_Xb + (size_t)(bi + row) * DIM + k0 + off);
            cp16((unsigned int)__cvta_generic_to_shared(&sB[buf][row][off]),
                 g_Xb + (size_t)(bj + row) * DIM + k0 + off);
        }
    };

    load_stage(0, 0);
    cp_commit();
    cp_wait0();
    __syncthreads();

    for (int s = 0; s < DIM / 32; s++) {
        const int cbuf = s & 1;
        if (s + 1 < DIM / 32) {
            load_stage((s + 1) & 1, (s + 1) * 32);
            cp_commit();
        }
#pragma unroll
        for (int ks = 0; ks < 2; ks++) {
            unsigned int a[4][4], bb[4][2];
#pragma unroll
            for (int mt = 0; mt < 4; mt++) {
                unsigned int addr = (unsigned int)__cvta_generic_to_shared(
                    &sA[cbuf][wm + mt * 16 + (lane & 15)][ks * 16 + (lane >> 4) * 8]);
                asm volatile("ldmatrix.sync.aligned.m8n8.x4.shared.b16 {%0,%1,%2,%3}, [%4];"
                             : "=r"(a[mt][0]), "=r"(a[mt][1]), "=r"(a[mt][2]), "=r"(a[mt][3])
                             : "r"(addr));
            }
#pragma unroll
            for (int nt = 0; nt < 4; nt++) {
                unsigned int addr = (unsigned int)__cvta_generic_to_shared(
                    &sB[cbuf][wn + nt * 8 + (lane & 7)][ks * 16 + ((lane >> 3) & 1) * 8]);
                asm volatile("ldmatrix.sync.aligned.m8n8.x2.shared.b16 {%0,%1}, [%2];"
                             : "=r"(bb[nt][0]), "=r"(bb[nt][1]) : "r"(addr));
            }
#pragma unroll
            for (int mt = 0; mt < 4; mt++)
#pragma unroll
                for (int nt = 0; nt < 4; nt++) {
                    asm volatile(
                        "mma.sync.aligned.m16n8k16.row.col.f32.bf16.bf16.f32 "
                        "{%0,%1,%2,%3},{%4,%5,%6,%7},{%8,%9},{%0,%1,%2,%3};"
                        : "+f"(acc[mt][nt][0]), "+f"(acc[mt][nt][1]),
                          "+f"(acc[mt][nt][2]), "+f"(acc[mt][nt][3])
                        : "r"(a[mt][0]), "r"(a[mt][1]), "r"(a[mt][2]), "r"(a[mt][3]),
                          "r"(bb[nt][0]), "r"(bb[nt][1]));
                }
        }
        if (s + 1 < DIM / 32) cp_wait0();
        __syncthreads();
    }

#pragma unroll
    for (int mt = 0; mt < 4; mt++) {
#pragma unroll
        for (int nt = 0; nt < 4; nt++) {
            int r0 = bi + wm + mt * 16 + (lane >> 2);
            int c0 = bj + wn + nt * 8 + (lane & 3) * 2;
            *(float2*)(g_SIM + (size_t)r0 * NROW + c0) =
                make_float2(acc[mt][nt][0], acc[mt][nt][1]);
            *(float2*)(g_SIM + (size_t)(r0 + 8) * NROW + c0) =
                make_float2(acc[mt][nt][2], acc[mt][nt][3]);
        }
    }

    if (p != q) {
        for (int cc = 0; cc < 4; cc++) {
            __syncthreads();
            if ((wid & 3) == cc) {
#pragma unroll
                for (int mt = 0; mt < 4; mt++)
#pragma unroll
                    for (int nt = 0; nt < 4; nt++) {
                        int r0 = wm + mt * 16 + (lane >> 2);
                        int c0 = nt * 8 + (lane & 3) * 2;
                        tr[c0    ][r0    ] = acc[mt][nt][0];
                        tr[c0 + 1][r0    ] = acc[mt][nt][1];
                        tr[c0    ][r0 + 8] = acc[mt][nt][2];
                        tr[c0 + 1][r0 + 8] = acc[mt][nt][3];
                    }
            }
            __syncthreads();
            const int c = t >> 3;
            const int r = (t & 7) * 16;
            float* dst = g_SIM + (size_t)(bj + cc * 32 + c) * NROW + bi + r;
#pragma unroll
            for (int k = 0; k < 4; k++)
                *(float4*)(dst + k * 4) = *(float4*)(&tr[c][r + k * 4]);
        }
    }
}

// ---------------------------------------------------------------------------
// Per-row loss: ONE smem key array (f2k of every element) + neg/pos bitmasks.
// Same selection algorithm as the R8-proven version (round-0 fused histogram,
// round-1, 16-bit-prefix candidate shortcut, exact radix fallback).
__global__ __launch_bounds__(NT) void row_loss_kernel() {
    __shared__ unsigned int s_k[NROW];      // 16 KB: f2k(sim) for ALL elements
    __shared__ unsigned int s_nm[128];      // neg bitmask (1 bit / element)
    __shared__ unsigned int s_pm[128];      // pos-excl-self bitmask
    __shared__ unsigned int s_hist[256];
    __shared__ unsigned int s_cand[256];
    __shared__ unsigned int s_wtot[8];
    __shared__ float        s_red[8];
    __shared__ unsigned int sh_sel, sh_r, sh_h, sh_cnt;
    __shared__ unsigned int sh_key, sh_m;

    const int i    = blockIdx.x;
    const int t    = threadIdx.x;
    const int lane = t & 31;
    const int wid  = t >> 5;
    const unsigned char myc = g_cls[i];
    const float* row = g_SIM + (size_t)i * NROW;

    s_hist[t] = 0;
    if (t < 128) { s_nm[t] = 0; s_pm[t] = 0; }
    __syncthreads();

    // ---- load pass: keys + bitmasks + round-0 histogram + K + pos_max ----
    float pmax = -1e30f;
    int   kneg = 0;
#pragma unroll
    for (int c = 0; c < 4; c++) {
        const int j0 = (c * NT + t) * 4;
        float4 v4 = *(const float4*)(row + j0);
        uchar4 c4 = *(const uchar4*)(g_cls + j0);
        float vv[4] = {v4.x, v4.y, v4.z, v4.w};
        unsigned char cc[4] = {c4.x, c4.y, c4.z, c4.w};
        unsigned int kk[4];
        unsigned int nb = 0, pb = 0;
#pragma unroll
        for (int e = 0; e < 4; e++) {
            const int idx = j0 + e;
            kk[e] = f2k(vv[e]);
            if (cc[e] != myc) {
                nb |= (1u << e);
                kneg++;
                atomicAdd(&s_hist[kk[e] >> 24], 1u);
            } else if (idx != i) {
                pb |= (1u << e);
                pmax = fmaxf(pmax, vv[e]);
            }
        }
        *(uint4*)(s_k + j0) = make_uint4(kk[0], kk[1], kk[2], kk[3]);
        const int word = c * 32 + (t >> 3);
        const int shp  = (t & 7) * 4;
        if (nb) atomicOr(&s_nm[word], nb << shp);
        if (pb) atomicOr(&s_pm[word], pb << shp);
    }
#pragma unroll
    for (int o = 16; o > 0; o >>= 1) {
        kneg += __shfl_xor_sync(0xFFFFFFFFu, kneg, o);
        pmax  = fmaxf(pmax, __shfl_xor_sync(0xFFFFFFFFu, pmax, o));
    }
    if (lane == 0) { s_wtot[wid] = (unsigned int)kneg; s_red[wid] = pmax; }
    __syncthreads();
    unsigned int K = 0; float pm = -1e30f;
#pragma unroll
    for (int w = 0; w < 8; w++) { K += s_wtot[w]; pm = fmaxf(pm, s_red[w]); }
    const int drop = max((int)floorf((float)K * 0.05f), 1);
    unsigned int r = (unsigned int)(drop + 1);

    auto select_bucket = [&](unsigned int rr) {
        const unsigned int h = s_hist[t];
        unsigned int suf = h;
#pragma unroll
        for (int o = 1; o < 32; o <<= 1) {
            const unsigned int w = __shfl_down_sync(0xFFFFFFFFu, suf, o);
            if (lane + o < 32) suf += w;
        }
        if (lane == 0) s_wtot[wid] = suf;
        __syncthreads();
#pragma unroll
        for (int w = 0; w < 8; w++) if (w > wid) suf += s_wtot[w];
        if (suf >= rr && (suf - h) < rr) {
            sh_sel = (unsigned int)t;
            sh_r   = rr - (suf - h);
            sh_h   = h;
        }
        __syncthreads();
    };

    // ---- round 0 (hist already built) ----
    select_bucket(r);
    unsigned int prefix = sh_sel;
    r = sh_r;
    __syncthreads();

    // ---- round 1 ----
    s_hist[t] = 0;
    __syncthreads();
#pragma unroll
    for (int c = 0; c < 4; c++) {
        const int j0 = (c * NT + t) * 4;
        uint4 k4 = *(const uint4*)(s_k + j0);
        unsigned int kk[4] = {k4.x, k4.y, k4.z, k4.w};
        const unsigned int nn = (s_nm[c * 32 + (t >> 3)] >> ((t & 7) * 4)) & 0xFu;
#pragma unroll
        for (int e = 0; e < 4; e++)
            if (((nn >> e) & 1u) && (kk[e] >> 24) == prefix)
                atomicAdd(&s_hist[(kk[e] >> 16) & 255u], 1u);
    }
    __syncthreads();
    select_bucket(r);
    prefix = (prefix << 8) | sh_sel;
    r = sh_r;
    __syncthreads();

    // ---- candidate collection for low 16 bits ----
    if (t == 0) sh_cnt = 0;
    __syncthreads();
#pragma unroll
    for (int c = 0; c < 4; c++) {
        const int j0 = (c * NT + t) * 4;
        uint4 k4 = *(const uint4*)(s_k + j0);
        unsigned int kk[4] = {k4.x, k4.y, k4.z, k4.w};
        const unsigned int nn = (s_nm[c * 32 + (t >> 3)] >> ((t & 7) * 4)) & 0xFu;
#pragma unroll
        for (int e = 0; e < 4; e++)
            if (((nn >> e) & 1u) && (kk[e] >> 16) == prefix) {
                unsigned int pslot = atomicAdd(&sh_cnt, 1u);
                if (pslot < 256) s_cand[pslot] = kk[e];
            }
    }
    __syncthreads();

    if (sh_cnt <= 256u) {
        const unsigned int C = sh_cnt;
        if (t < (int)C) {
            const unsigned int k = s_cand[t];
            unsigned int cg = 0, ce = 0;
            for (unsigned int j = 0; j < C; j++) {
                const unsigned int kj = s_cand[j];
                cg += (kj > k); ce += (kj == k);
            }
            if (cg < r && r <= cg + ce) {
                sh_key = k;
                sh_m   = ce + 1u - (r - cg);
            }
        }
        __syncthreads();
    } else {
        // exact fallback: full radix rounds 2 and 3
#pragma unroll
        for (int shift = 8; shift >= 0; shift -= 8) {
            s_hist[t] = 0;
            __syncthreads();
#pragma unroll
            for (int c = 0; c < 4; c++) {
                const int j0 = (c * NT + t) * 4;
                uint4 k4 = *(const uint4*)(s_k + j0);
                unsigned int kk[4] = {k4.x, k4.y, k4.z, k4.w};
                const unsigned int nn = (s_nm[c * 32 + (t >> 3)] >> ((t & 7) * 4)) & 0xFu;
#pragma unroll
                for (int e = 0; e < 4; e++)
                    if (((nn >> e) & 1u) && (kk[e] >> (shift + 8)) == prefix)
                        atomicAdd(&s_hist[(kk[e] >> shift) & 255u], 1u);
            }
            __syncthreads();
            select_bucket(r);
            prefix = (prefix << 8) | sh_sel;
            r = sh_r;
            if (t == 0 && shift == 0) { sh_key = prefix; sh_m = sh_h + 1u - sh_r; }
            __syncthreads();
        }
    }

    const float T = k2f(sh_key);                 // == neg_thresh exactly
    const int   m = (int)sh_m;                   // # kept negatives equal to T

    // ---- fused final pass: pos_loss + neg_sum (values via k2f) ----
    const float thr   = T + 0.1f;
    const float lower = fmaxf(0.6f, pm) - 0.1f;
    float ploss = 0.f, ns = 0.f;
#pragma unroll
    for (int c = 0; c < 4; c++) {
        const int j0 = (c * NT + t) * 4;
        uint4 k4 = *(const uint4*)(s_k + j0);
        unsigned int kk[4] = {k4.x, k4.y, k4.z, k4.w};
        const unsigned int mw = s_nm[c * 32 + (t >> 3)];
        const unsigned int pw = s_pm[c * 32 + (t >> 3)];
        const unsigned int nn = (mw >> ((t & 7) * 4)) & 0xFu;
        const unsigned int pp = (pw >> ((t & 7) * 4)) & 0xFu;
#pragma unroll
        for (int e = 0; e < 4; e++) {
            const float v = k2f(kk[e]);
            if (((nn >> e) & 1u) && v < T && v > lower) ns += v;
            if (((pp >> e) & 1u) && v < thr) ploss += 1.0f - v;
        }
    }
#pragma unroll
    for (int o = 16; o > 0; o >>= 1) {
        ploss += __shfl_xor_sync(0xFFFFFFFFu, ploss, o);
        ns    += __shfl_xor_sync(0xFFFFFFFFu, ns, o);
    }
    if (lane == 0) { s_red[wid] = ploss; s_wtot[wid] = __float_as_uint(ns); }
    __syncthreads();

    if (t == 0) {
        float pl = 0.f, nss = 0.f;
#pragma unroll
        for (int w = 0; w < 8; w++) { pl += s_red[w]; nss += __uint_as_float(s_wtot[w]); }
        float loss = 0.f;
        if (pm > -1e29f) {                       // has_pos
            loss = pl + nss;
            if (T > lower) loss += (float)m * T; // ties at threshold (kept copies)
        }
        g_rowloss[i] = loss;
    }
}

// ---------------------------------------------------------------------------
__global__ void finalize_kernel(float* __restrict__ out) {
    __shared__ float s[1024];
    int t = threadIdx.x;
    float a = 0.f;
    for (int j = t; j < NROW; j += 1024) a += g_rowloss[j];
    s[t] = a; __syncthreads();
    for (int o = 512; o > 0; o >>= 1) { if (t < o) s[t] += s[t + o]; __syncthreads(); }
    if (t == 0) out[0] = s[0] / (float)NROW;
}

// ---------------------------------------------------------------------------
extern "C" void kernel_launch(void* const* d_in, const int* in_sizes, int n_in,
                              void* d_out, int out_size) {
    const float* emb   = (const float*)d_in[0];
    const int*   tgt32 = (const int*)d_in[1];
    float* out = (float*)d_out;

    cls_kernel<<<1, 1024>>>(tgt32);
    normalize_kernel<<<NROW, 256>>>(emb);
    gemm_kernel<<<528, 256>>>();
    row_loss_kernel<<<NROW, NT>>>();
    finalize_kernel<<<1, 1024>>>(out);
}

// round 13
// speedup vs baseline: 1.0996x; 1.0114x over previous
#include <cuda_runtime.h>
#include <cuda_bf16.h>
#include <stdint.h>

#define NROW 4096
#define DIM  1024
#define NT   256
#define RS   40          // padded smem row stride (bf16 elems) for conflict-free ldmatrix

// Static device scratch (no runtime allocation allowed).
__device__ __nv_bfloat16 g_Xb[(size_t)NROW * DIM];   // 8 MB normalized embeddings (bf16)
__device__ float g_SIM[(size_t)NROW * NROW];         // 64 MB similarity matrix
__device__ unsigned char g_cls[NROW];
__device__ float g_rowloss[NROW];
__device__ unsigned int g_done;                      // last-block counter

// Monotone fp32 <-> uint32 key (ascending order preserved)
__device__ __forceinline__ unsigned int f2k(float f) {
    unsigned int u = __float_as_uint(f);
    return (u & 0x80000000u) ? ~u : (u | 0x80000000u);
}
__device__ __forceinline__ float k2f(unsigned int k) {
    unsigned int u = (k & 0x80000000u) ? (k & 0x7FFFFFFFu) : ~k;
    return __uint_as_float(u);
}

// ---------------------------------------------------------------------------
// normalize (blocks 0..4095) + fused class extraction (block 4096).
// Classes: reference declares int64 targets, but JAX without x64 emits int32.
// Sniff layout: if ALL odd int32 words are zero -> little-endian int64.
__global__ __launch_bounds__(256) void normalize_kernel(const float* __restrict__ emb,
                                                        const int* __restrict__ tgt32) {
    const int i = blockIdx.x;
    const int t = threadIdx.x;

    if (i == NROW) {
        // ---- class block: dtype sniff + extraction + counter reset ----
        __shared__ int s_any;
        if (t == 0) { s_any = 0; g_done = 0u; }
        __syncthreads();
        int any = 0;
        for (int j = t; j < NROW / 2; j += 256)
            any |= (tgt32[2 * j + 1] != 0);
        if (any) atomicOr(&s_any, 1);
        __syncthreads();
        const bool is64 = (s_any == 0);
        for (int j = t; j < NROW; j += 256)
            g_cls[j] = (unsigned char)(is64 ? tgt32[2 * j] : tgt32[j]);
        return;
    }

    const int lane = t & 31;
    const int wid  = t >> 5;
    __shared__ float s[8];

    float4 v = *(const float4*)(emb + (size_t)i * DIM + t * 4);
    float ss = v.x * v.x + v.y * v.y + v.z * v.z + v.w * v.w;
#pragma unroll
    for (int o = 16; o > 0; o >>= 1) ss += __shfl_xor_sync(0xFFFFFFFFu, ss, o);
    if (lane == 0) s[wid] = ss;
    __syncthreads();
    float tot = 0.f;
#pragma unroll
    for (int w = 0; w < 8; w++) tot += s[w];
    const float norm = fmaxf(sqrtf(tot), 1e-12f);

    unsigned int u0 = (unsigned int)__bfloat16_as_ushort(__float2bfloat16(v.x / norm));
    unsigned int u1 = (unsigned int)__bfloat16_as_ushort(__float2bfloat16(v.y / norm));
    unsigned int u2 = (unsigned int)__bfloat16_as_ushort(__float2bfloat16(v.z / norm));
    unsigned int u3 = (unsigned int)__bfloat16_as_ushort(__float2bfloat16(v.w / norm));
    uint2 pk;
    pk.x = u0 | (u1 << 16);
    pk.y = u2 | (u3 << 16);
    *(uint2*)(g_Xb + (size_t)i * DIM + t * 4) = pk;
}

// ---------------------------------------------------------------------------
// SIM = X * X^T in bf16 tensor cores (R8-proven). SYMMETRIC: 528 lower-
// triangular 128x128 tiles; off-diagonal tiles also store their transpose,
// staged via smem so all global stores stay coalesced.
__device__ __forceinline__ void cp16(unsigned int smem_dst, const void* gsrc) {
    asm volatile("cp.async.cg.shared.global [%0], [%1], 16;\n" :: "r"(smem_dst), "l"(gsrc));
}
__device__ __forceinline__ void cp_commit() { asm volatile("cp.async.commit_group;\n"); }
__device__ __forceinline__ void cp_wait0() { asm volatile("cp.async.wait_group 0;\n"); }

__global__ __launch_bounds__(256) void gemm_kernel() {
    __shared__ __align__(16) char smbuf[2 * 128 * RS * 2 * 2];
    typedef __nv_bfloat16 Tile[128][RS];
    Tile* sA = reinterpret_cast<Tile*>(smbuf);
    Tile* sB = reinterpret_cast<Tile*>(smbuf + 2 * 128 * RS * 2);
    float (*tr)[132] = reinterpret_cast<float (*)[132]>(smbuf);

    const int t    = threadIdx.x;
    const int lane = t & 31;
    const int wid  = t >> 5;
    const int wm   = (wid >> 2) * 64;
    const int wn   = (wid & 3) * 32;

    const int b = blockIdx.x;
    int p = (int)((sqrtf(8.f * (float)b + 1.f) - 1.f) * 0.5f);
    while ((p + 1) * (p + 2) / 2 <= b) p++;
    while (p * (p + 1) / 2 > b) p--;
    const int q  = b - p * (p + 1) / 2;
    const int bi = p * 128;
    const int bj = q * 128;

    float acc[4][4][4];
#pragma unroll
    for (int mt = 0; mt < 4; mt++)
#pragma unroll
        for (int nt = 0; nt < 4; nt++)
#pragma unroll
            for (int r = 0; r < 4; r++) acc[mt][nt][r] = 0.f;

    auto load_stage = [&](int buf, int k0) {
#pragma unroll
        for (int c = t; c < 512; c += 256) {
            int row = c >> 2, off = (c & 3) * 8;
            cp16((unsigned int)__cvta_generic_to_shared(&sA[buf][row][off]),
                 g_Xb + (size_t)(bi + row) * DIM + k0 + off);
            cp16((unsigned int)__cvta_generic_to_shared(&sB[buf][row][off]),
                 g_Xb + (size_t)(bj + row) * DIM + k0 + off);
        }
    };

    load_stage(0, 0);
    cp_commit();
    cp_wait0();
    __syncthreads();

    for (int s = 0; s < DIM / 32; s++) {
        const int cbuf = s & 1;
        if (s + 1 < DIM / 32) {
            load_stage((s + 1) & 1, (s + 1) * 32);
            cp_commit();
        }
#pragma unroll
        for (int ks = 0; ks < 2; ks++) {
            unsigned int a[4][4], bb[4][2];
#pragma unroll
            for (int mt = 0; mt < 4; mt++) {
                unsigned int addr = (unsigned int)__cvta_generic_to_shared(
                    &sA[cbuf][wm + mt * 16 + (lane & 15)][ks * 16 + (lane >> 4) * 8]);
                asm volatile("ldmatrix.sync.aligned.m8n8.x4.shared.b16 {%0,%1,%2,%3}, [%4];"
                             : "=r"(a[mt][0]), "=r"(a[mt][1]), "=r"(a[mt][2]), "=r"(a[mt][3])
                             : "r"(addr));
            }
#pragma unroll
            for (int nt = 0; nt < 4; nt++) {
                unsigned int addr = (unsigned int)__cvta_generic_to_shared(
                    &sB[cbuf][wn + nt * 8 + (lane & 7)][ks * 16 + ((lane >> 3) & 1) * 8]);
                asm volatile("ldmatrix.sync.aligned.m8n8.x2.shared.b16 {%0,%1}, [%2];"
                             : "=r"(bb[nt][0]), "=r"(bb[nt][1]) : "r"(addr));
            }
#pragma unroll
            for (int mt = 0; mt < 4; mt++)
#pragma unroll
                for (int nt = 0; nt < 4; nt++) {
                    asm volatile(
                        "mma.sync.aligned.m16n8k16.row.col.f32.bf16.bf16.f32 "
                        "{%0,%1,%2,%3},{%4,%5,%6,%7},{%8,%9},{%0,%1,%2,%3};"
                        : "+f"(acc[mt][nt][0]), "+f"(acc[mt][nt][1]),
                          "+f"(acc[mt][nt][2]), "+f"(acc[mt][nt][3])
                        : "r"(a[mt][0]), "r"(a[mt][1]), "r"(a[mt][2]), "r"(a[mt][3]),
                          "r"(bb[nt][0]), "r"(bb[nt][1]));
                }
        }
        if (s + 1 < DIM / 32) cp_wait0();
        __syncthreads();
    }

#pragma unroll
    for (int mt = 0; mt < 4; mt++) {
#pragma unroll
        for (int nt = 0; nt < 4; nt++) {
            int r0 = bi + wm + mt * 16 + (lane >> 2);
            int c0 = bj + wn + nt * 8 + (lane & 3) * 2;
            *(float2*)(g_SIM + (size_t)r0 * NROW + c0) =
                make_float2(acc[mt][nt][0], acc[mt][nt][1]);
            *(float2*)(g_SIM + (size_t)(r0 + 8) * NROW + c0) =
                make_float2(acc[mt][nt][2], acc[mt][nt][3]);
        }
    }

    if (p != q) {
        for (int cc = 0; cc < 4; cc++) {
            __syncthreads();
            if ((wid & 3) == cc) {
#pragma unroll
                for (int mt = 0; mt < 4; mt++)
#pragma unroll
                    for (int nt = 0; nt < 4; nt++) {
                        int r0 = wm + mt * 16 + (lane >> 2);
                        int c0 = nt * 8 + (lane & 3) * 2;
                        tr[c0    ][r0    ] = acc[mt][nt][0];
                        tr[c0 + 1][r0    ] = acc[mt][nt][1];
                        tr[c0    ][r0 + 8] = acc[mt][nt][2];
                        tr[c0 + 1][r0 + 8] = acc[mt][nt][3];
                    }
            }
            __syncthreads();
            const int c = t >> 3;
            const int r = (t & 7) * 16;
            float* dst = g_SIM + (size_t)(bj + cc * 32 + c) * NROW + bi + r;
#pragma unroll
            for (int k = 0; k < 4; k++)
                *(float4*)(dst + k * 4) = *(float4*)(&tr[c][r + k * 4]);
        }
    }
}

// ---------------------------------------------------------------------------
// Per-row loss (R8-proven core) + fused last-block final reduction.
__global__ __launch_bounds__(NT) void row_loss_kernel(float* __restrict__ out) {
    __shared__ unsigned int s_k[NROW];      // 16 KB
    __shared__ float        s_p[NROW];      // 16 KB
    __shared__ unsigned int s_hist[256];
    __shared__ unsigned int s_cand[256];
    __shared__ unsigned int s_wtot[8];
    __shared__ float        s_red[8];
    __shared__ unsigned int sh_sel, sh_r, sh_h, sh_cnt;
    __shared__ unsigned int sh_key, sh_m;
    __shared__ int          sh_last;

    const int i    = blockIdx.x;
    const int t    = threadIdx.x;
    const int lane = t & 31;
    const int wid  = t >> 5;
    const unsigned char myc = g_cls[i];
    const float* row = g_SIM + (size_t)i * NROW;

    s_hist[t] = 0;
    __syncthreads();

    // ---- load pass: fill s_k/s_p, round-0 histogram, K count, pos_max ----
    float pmax = -1e30f;
    int   kneg = 0;
#pragma unroll
    for (int c = 0; c < 4; c++) {
        const int j0 = (c * NT + t) * 4;
        float4 v4 = *(const float4*)(row + j0);
        uchar4 c4 = *(const uchar4*)(g_cls + j0);
        float vv[4] = {v4.x, v4.y, v4.z, v4.w};
        unsigned char cc[4] = {c4.x, c4.y, c4.z, c4.w};
        unsigned int kk[4];
        float        pp[4];
#pragma unroll
        for (int e = 0; e < 4; e++) {
            const int idx = j0 + e;
            if (cc[e] != myc) {
                const unsigned int key = f2k(vv[e]);
                kk[e] = key; pp[e] = -1e30f;
                kneg++;
                atomicAdd(&s_hist[key >> 24], 1u);
            } else {
                kk[e] = 0u;
                pp[e] = (idx != i) ? vv[e] : -1e30f;
                pmax = fmaxf(pmax, pp[e]);
            }
        }
        *(uint4*)(s_k + j0)  = make_uint4(kk[0], kk[1], kk[2], kk[3]);
        *(float4*)(s_p + j0) = make_float4(pp[0], pp[1], pp[2], pp[3]);
    }
#pragma unroll
    for (int o = 16; o > 0; o >>= 1) {
        kneg += __shfl_xor_sync(0xFFFFFFFFu, kneg, o);
        pmax  = fmaxf(pmax, __shfl_xor_sync(0xFFFFFFFFu, pmax, o));
    }
    if (lane == 0) { s_wtot[wid] = (unsigned int)kneg; s_red[wid] = pmax; }
    __syncthreads();
    unsigned int K = 0; float pm = -1e30f;
#pragma unroll
    for (int w = 0; w < 8; w++) { K += s_wtot[w]; pm = fmaxf(pm, s_red[w]); }
    const int drop = max((int)floorf((float)K * 0.05f), 1);
    unsigned int r = (unsigned int)(drop + 1);

    auto select_bucket = [&](unsigned int rr) {
        const unsigned int h = s_hist[t];
        unsigned int suf = h;
#pragma unroll
        for (int o = 1; o < 32; o <<= 1) {
            const unsigned int w = __shfl_down_sync(0xFFFFFFFFu, suf, o);
            if (lane + o < 32) suf += w;
        }
        if (lane == 0) s_wtot[wid] = suf;
        __syncthreads();
#pragma unroll
        for (int w = 0; w < 8; w++) if (w > wid) suf += s_wtot[w];
        if (suf >= rr && (suf - h) < rr) {
            sh_sel = (unsigned int)t;
            sh_r   = rr - (suf - h);
            sh_h   = h;
        }
        __syncthreads();
    };

    // ---- round 0 (hist already built) ----
    select_bucket(r);
    unsigned int prefix = sh_sel;
    r = sh_r;
    __syncthreads();

    // ---- round 1 ----
    s_hist[t] = 0;
    __syncthreads();
#pragma unroll
    for (int c = 0; c < 4; c++) {
        uint4 k4 = *(const uint4*)(s_k + (c * NT + t) * 4);
        unsigned int kk[4] = {k4.x, k4.y, k4.z, k4.w};
#pragma unroll
        for (int e = 0; e < 4; e++)
            if ((kk[e] >> 24) == prefix)
                atomicAdd(&s_hist[(kk[e] >> 16) & 255u], 1u);
    }
    __syncthreads();
    select_bucket(r);
    prefix = (prefix << 8) | sh_sel;
    r = sh_r;
    __syncthreads();

    // ---- candidate collection for low 16 bits ----
    if (t == 0) sh_cnt = 0;
    __syncthreads();
#pragma unroll
    for (int c = 0; c < 4; c++) {
        uint4 k4 = *(const uint4*)(s_k + (c * NT + t) * 4);
        unsigned int kk[4] = {k4.x, k4.y, k4.z, k4.w};
#pragma unroll
        for (int e = 0; e < 4; e++)
            if ((kk[e] >> 16) == prefix) {
                unsigned int pslot = atomicAdd(&sh_cnt, 1u);
                if (pslot < 256) s_cand[pslot] = kk[e];
            }
    }
    __syncthreads();

    if (sh_cnt <= 256u) {
        const unsigned int C = sh_cnt;
        if (t < (int)C) {
            const unsigned int k = s_cand[t];
            unsigned int cg = 0, ce = 0;
            for (unsigned int j = 0; j < C; j++) {
                const unsigned int kj = s_cand[j];
                cg += (kj > k); ce += (kj == k);
            }
            if (cg < r && r <= cg + ce) {
                sh_key = k;
                sh_m   = ce + 1u - (r - cg);
            }
        }
        __syncthreads();
    } else {
        // exact fallback: full radix rounds 2 and 3
#pragma unroll
        for (int shift = 8; shift >= 0; shift -= 8) {
            s_hist[t] = 0;
            __syncthreads();
#pragma unroll
            for (int c = 0; c < 4; c++) {
                uint4 k4 = *(const uint4*)(s_k + (c * NT + t) * 4);
                unsigned int kk[4] = {k4.x, k4.y, k4.z, k4.w};
#pragma unroll
                for (int e = 0; e < 4; e++)
                    if ((kk[e] >> (shift + 8)) == prefix)
                        atomicAdd(&s_hist[(kk[e] >> shift) & 255u], 1u);
            }
            __syncthreads();
            select_bucket(r);
            prefix = (prefix << 8) | sh_sel;
            r = sh_r;
            if (t == 0 && shift == 0) { sh_key = prefix; sh_m = sh_h + 1u - sh_r; }
            __syncthreads();
        }
    }

    const float T = k2f(sh_key);                 // == neg_thresh exactly
    const int   m = (int)sh_m;                   // # kept negatives equal to T

    // ---- fused final pass: pos_loss + neg_sum ----
    const float thr   = T + 0.1f;
    const float lower = fmaxf(0.6f, pm) - 0.1f;
    float ploss = 0.f, ns = 0.f;
#pragma unroll
    for (int c = 0; c < 4; c++) {
        const int j0 = (c * NT + t) * 4;
        uint4  k4 = *(const uint4*)(s_k + j0);
        float4 p4 = *(const float4*)(s_p + j0);
        unsigned int kk[4] = {k4.x, k4.y, k4.z, k4.w};
        float        pp[4] = {p4.x, p4.y, p4.z, p4.w};
#pragma unroll
        for (int e = 0; e < 4; e++) {
            if (kk[e]) {
                const float v = k2f(kk[e]);
                if (v < T && v > lower) ns += v;
            }
            if (pp[e] > -1e29f && pp[e] < thr) ploss += 1.0f - pp[e];
        }
    }
#pragma unroll
    for (int o = 16; o > 0; o >>= 1) {
        ploss += __shfl_xor_sync(0xFFFFFFFFu, ploss, o);
        ns    += __shfl_xor_sync(0xFFFFFFFFu, ns, o);
    }
    if (lane == 0) { s_red[wid] = ploss; s_wtot[wid] = __float_as_uint(ns); }
    __syncthreads();

    if (t == 0) {
        float pl = 0.f, nss = 0.f;
#pragma unroll
        for (int w = 0; w < 8; w++) { pl += s_red[w]; nss += __uint_as_float(s_wtot[w]); }
        float loss = 0.f;
        if (pm > -1e29f) {                       // has_pos
            loss = pl + nss;
            if (T > lower) loss += (float)m * T; // ties at threshold (kept copies)
        }
        g_rowloss[i] = loss;
        __threadfence();
        const unsigned int old = atomicAdd(&g_done, 1u);
        sh_last = (old == (unsigned int)(NROW - 1));
    }
    __syncthreads();

    // ---- last block: deterministic fixed-order final reduction ----
    if (sh_last) {
        float a = 0.f;
        for (int j = t; j < NROW; j += NT) a += g_rowloss[j];
        // reuse s_p as reduction scratch
        s_p[t] = a;
        __syncthreads();
        for (int o = NT / 2; o > 0; o >>= 1) {
            if (t < o) s_p[t] += s_p[t + o];
            __syncthreads();
        }
        if (t == 0) out[0] = s_p[0] / (float)NROW;
    }
}

// ---------------------------------------------------------------------------
extern "C" void kernel_launch(void* const* d_in, const int* in_sizes, int n_in,
                              void* d_out, int out_size) {
    const float* emb   = (const float*)d_in[0];
    const int*   tgt32 = (const int*)d_in[1];
    float* out = (float*)d_out;

    normalize_kernel<<<NROW + 1, 256>>>(emb, tgt32);
    gemm_kernel<<<528, 256>>>();
    row_loss_kernel<<<NROW, NT>>>(out);
}

// round 14
// speedup vs baseline: 1.2056x; 1.0964x over previous
#include <cuda_runtime.h>
#include <cuda_bf16.h>
#include <stdint.h>

#define NROW 4096
#define DIM  1024
#define NT   256
#define RS   40          // padded smem row stride (bf16 elems) for conflict-free ldmatrix

// Static device scratch (no runtime allocation allowed).
__device__ __nv_bfloat16 g_Xb[(size_t)NROW * DIM];     // 8 MB normalized embeddings
__device__ __nv_bfloat16 g_SIMh[(size_t)NROW * NROW];  // 32 MB similarity matrix (bf16)
__device__ unsigned char g_cls[NROW];
__device__ float g_rowloss[NROW];

// Monotone bf16-bits <-> 16-bit key (ascending order preserved)
__device__ __forceinline__ unsigned int h2k(unsigned int u) {   // u = bf16 bits (16)
    return (u & 0x8000u) ? ((~u) & 0xFFFFu) : (u | 0x8000u);
}
__device__ __forceinline__ float k2f16(unsigned int k) {
    unsigned int u = (k & 0x8000u) ? (k & 0x7FFFu) : ((~k) & 0xFFFFu);
    return __uint_as_float(u << 16);
}
__device__ __forceinline__ float h2f(unsigned int u) {          // bf16 bits -> float
    return __uint_as_float(u << 16);
}

// ---------------------------------------------------------------------------
// Classes: reference declares int64 targets, but JAX without x64 emits int32.
__global__ __launch_bounds__(1024) void cls_kernel(const int* __restrict__ tgt32) {
    __shared__ int s_any;
    const int t = threadIdx.x;
    if (t == 0) s_any = 0;
    __syncthreads();
    int any = 0;
    for (int j = t; j < NROW / 2; j += 1024)
        any |= (tgt32[2 * j + 1] != 0);
    if (any) atomicOr(&s_any, 1);
    __syncthreads();
    const bool is64 = (s_any == 0);
    for (int i = t; i < NROW; i += 1024)
        g_cls[i] = (unsigned char)(is64 ? tgt32[2 * i] : tgt32[i]);
}

// ---------------------------------------------------------------------------
// Single-pass normalize: each thread owns one float4 of the row.
__global__ __launch_bounds__(256) void normalize_kernel(const float* __restrict__ emb) {
    const int i = blockIdx.x;
    const int t = threadIdx.x;
    const int lane = t & 31;
    const int wid  = t >> 5;
    __shared__ float s[8];

    float4 v = *(const float4*)(emb + (size_t)i * DIM + t * 4);
    float ss = v.x * v.x + v.y * v.y + v.z * v.z + v.w * v.w;
#pragma unroll
    for (int o = 16; o > 0; o >>= 1) ss += __shfl_xor_sync(0xFFFFFFFFu, ss, o);
    if (lane == 0) s[wid] = ss;
    __syncthreads();
    float tot = 0.f;
#pragma unroll
    for (int w = 0; w < 8; w++) tot += s[w];
    const float norm = fmaxf(sqrtf(tot), 1e-12f);

    unsigned int u0 = (unsigned int)__bfloat16_as_ushort(__float2bfloat16(v.x / norm));
    unsigned int u1 = (unsigned int)__bfloat16_as_ushort(__float2bfloat16(v.y / norm));
    unsigned int u2 = (unsigned int)__bfloat16_as_ushort(__float2bfloat16(v.z / norm));
    unsigned int u3 = (unsigned int)__bfloat16_as_ushort(__float2bfloat16(v.w / norm));
    uint2 pk;
    pk.x = u0 | (u1 << 16);
    pk.y = u2 | (u3 << 16);
    *(uint2*)(g_Xb + (size_t)i * DIM + t * 4) = pk;
}

// ---------------------------------------------------------------------------
// SIM = X * X^T in bf16 tensor cores (R8-proven mainloop). SYMMETRIC: 528
// lower-triangular 128x128 tiles; off-diagonal tiles also store their
// transpose via smem staging. OUTPUT IS bf16.
__device__ __forceinline__ void cp16(unsigned int smem_dst, const void* gsrc) {
    asm volatile("cp.async.cg.shared.global [%0], [%1], 16;\n" :: "r"(smem_dst), "l"(gsrc));
}
__device__ __forceinline__ void cp_commit() { asm volatile("cp.async.commit_group;\n"); }
__device__ __forceinline__ void cp_wait0() { asm volatile("cp.async.wait_group 0;\n"); }

__global__ __launch_bounds__(256) void gemm_kernel() {
    __shared__ __align__(16) char smbuf[2 * 128 * RS * 2 * 2];
    typedef __nv_bfloat16 Tile[128][RS];
    Tile* sA = reinterpret_cast<Tile*>(smbuf);
    Tile* sB = reinterpret_cast<Tile*>(smbuf + 2 * 128 * RS * 2);
    float (*tr)[132] = reinterpret_cast<float (*)[132]>(smbuf);

    const int t    = threadIdx.x;
    const int lane = t & 31;
    const int wid  = t >> 5;
    const int wm   = (wid >> 2) * 64;
    const int wn   = (wid & 3) * 32;

    const int b = blockIdx.x;
    int p = (int)((sqrtf(8.f * (float)b + 1.f) - 1.f) * 0.5f);
    while ((p + 1) * (p + 2) / 2 <= b) p++;
    while (p * (p + 1) / 2 > b) p--;
    const int q  = b - p * (p + 1) / 2;
    const int bi = p * 128;
    const int bj = q * 128;

    float acc[4][4][4];
#pragma unroll
    for (int mt = 0; mt < 4; mt++)
#pragma unroll
        for (int nt = 0; nt < 4; nt++)
#pragma unroll
            for (int r = 0; r < 4; r++) acc[mt][nt][r] = 0.f;

    auto load_stage = [&](int buf, int k0) {
#pragma unroll
        for (int c = t; c < 512; c += 256) {
            int row = c >> 2, off = (c & 3) * 8;
            cp16((unsigned int)__cvta_generic_to_shared(&sA[buf][row][off]),
                 g_Xb + (size_t)(bi + row) * DIM + k0 + off);
            cp16((unsigned int)__cvta_generic_to_shared(&sB[buf][row][off]),
                 g_Xb + (size_t)(bj + row) * DIM + k0 + off);
        }
    };

    load_stage(0, 0);
    cp_commit();
    cp_wait0();
    __syncthreads();

    for (int s = 0; s < DIM / 32; s++) {
        const int cbuf = s & 1;
        if (s + 1 < DIM / 32) {
            load_stage((s + 1) & 1, (s + 1) * 32);
            cp_commit();
        }
#pragma unroll
        for (int ks = 0; ks < 2; ks++) {
            unsigned int a[4][4], bb[4][2];
#pragma unroll
            for (int mt = 0; mt < 4; mt++) {
                unsigned int addr = (unsigned int)__cvta_generic_to_shared(
                    &sA[cbuf][wm + mt * 16 + (lane & 15)][ks * 16 + (lane >> 4) * 8]);
                asm volatile("ldmatrix.sync.aligned.m8n8.x4.shared.b16 {%0,%1,%2,%3}, [%4];"
                             : "=r"(a[mt][0]), "=r"(a[mt][1]), "=r"(a[mt][2]), "=r"(a[mt][3])
                             : "r"(addr));
            }
#pragma unroll
            for (int nt = 0; nt < 4; nt++) {
                unsigned int addr = (unsigned int)__cvta_generic_to_shared(
                    &sB[cbuf][wn + nt * 8 + (lane & 7)][ks * 16 + ((lane >> 3) & 1) * 8]);
                asm volatile("ldmatrix.sync.aligned.m8n8.x2.shared.b16 {%0,%1}, [%2];"
                             : "=r"(bb[nt][0]), "=r"(bb[nt][1]) : "r"(addr));
            }
#pragma unroll
            for (int mt = 0; mt < 4; mt++)
#pragma unroll
                for (int nt = 0; nt < 4; nt++) {
                    asm volatile(
                        "mma.sync.aligned.m16n8k16.row.col.f32.bf16.bf16.f32 "
                        "{%0,%1,%2,%3},{%4,%5,%6,%7},{%8,%9},{%0,%1,%2,%3};"
                        : "+f"(acc[mt][nt][0]), "+f"(acc[mt][nt][1]),
                          "+f"(acc[mt][nt][2]), "+f"(acc[mt][nt][3])
                        : "r"(a[mt][0]), "r"(a[mt][1]), "r"(a[mt][2]), "r"(a[mt][3]),
                          "r"(bb[nt][0]), "r"(bb[nt][1]));
                }
        }
        if (s + 1 < DIM / 32) cp_wait0();
        __syncthreads();
    }

    // ---- direct store of (bi, bj) tile (bf16, coalesced) ----
#pragma unroll
    for (int mt = 0; mt < 4; mt++) {
#pragma unroll
        for (int nt = 0; nt < 4; nt++) {
            int r0 = bi + wm + mt * 16 + (lane >> 2);
            int c0 = bj + wn + nt * 8 + (lane & 3) * 2;
            __nv_bfloat162 p01 = __floats2bfloat162_rn(acc[mt][nt][0], acc[mt][nt][1]);
            __nv_bfloat162 p23 = __floats2bfloat162_rn(acc[mt][nt][2], acc[mt][nt][3]);
            *(__nv_bfloat162*)(g_SIMh + (size_t)r0 * NROW + c0) = p01;
            *(__nv_bfloat162*)(g_SIMh + (size_t)(r0 + 8) * NROW + c0) = p23;
        }
    }

    // ---- transposed store of (bj, bi) tile, staged via smem ----
    if (p != q) {
        for (int cc = 0; cc < 4; cc++) {
            __syncthreads();
            if ((wid & 3) == cc) {
#pragma unroll
                for (int mt = 0; mt < 4; mt++)
#pragma unroll
                    for (int nt = 0; nt < 4; nt++) {
                        int r0 = wm + mt * 16 + (lane >> 2);
                        int c0 = nt * 8 + (lane & 3) * 2;
                        tr[c0    ][r0    ] = acc[mt][nt][0];
                        tr[c0 + 1][r0    ] = acc[mt][nt][1];
                        tr[c0    ][r0 + 8] = acc[mt][nt][2];
                        tr[c0 + 1][r0 + 8] = acc[mt][nt][3];
                    }
            }
            __syncthreads();
            const int c = t >> 3;
            const int r = (t & 7) * 16;
            __nv_bfloat16* dst = g_SIMh + (size_t)(bj + cc * 32 + c) * NROW + bi + r;
#pragma unroll
            for (int k = 0; k < 4; k++) {
                float4 f = *(float4*)(&tr[c][r + k * 4]);
                __nv_bfloat162 lo = __floats2bfloat162_rn(f.x, f.y);
                __nv_bfloat162 hi = __floats2bfloat162_rn(f.z, f.w);
                uint2 w;
                w.x = *(unsigned int*)&lo;
                w.y = *(unsigned int*)&hi;
                *(uint2*)(dst + k * 4) = w;
            }
        }
    }
}

// ---------------------------------------------------------------------------
// Per-row loss on the bf16 SIM. 16-bit monotone keys -> EXACT radix select in
// just 2 rounds (top byte fused into load, low byte), no candidate stage.
__global__ __launch_bounds__(NT) void row_loss_kernel() {
    __shared__ __align__(16) unsigned short s_k[NROW];   // 8 KB: neg keys (0 = not neg)
    __shared__ __align__(16) unsigned short s_pv[NROW];  // 8 KB: pos bf16 bits (0xFF80 = none)
    __shared__ unsigned int s_hist[256];
    __shared__ unsigned int s_wtot[8];
    __shared__ float        s_red[8];
    __shared__ unsigned int sh_sel, sh_r, sh_h;

    const int i    = blockIdx.x;
    const int t    = threadIdx.x;
    const int lane = t & 31;
    const int wid  = t >> 5;
    const unsigned char myc = g_cls[i];
    const __nv_bfloat16* row = g_SIMh + (size_t)i * NROW;

    s_hist[t] = 0;
    __syncthreads();

    // ---- load pass: keys/posvals + round-0 histogram + K + pos_max ----
    float pmax = -1e30f;
    int   kneg = 0;
#pragma unroll
    for (int c = 0; c < 2; c++) {
        const int j0 = (c * NT + t) * 8;
        uint4 kv = *(const uint4*)(row + j0);          // 8 bf16
        uint2 cw = *(const uint2*)(g_cls + j0);        // 8 classes
        unsigned int hw[4] = {kv.x, kv.y, kv.z, kv.w};
        unsigned short kk[8], pp[8];
#pragma unroll
        for (int e = 0; e < 8; e++) {
            const unsigned int u  = (hw[e >> 1] >> ((e & 1) * 16)) & 0xFFFFu;
            const unsigned int cl = ((e < 4 ? cw.x : cw.y) >> ((e & 3) * 8)) & 0xFFu;
            if (cl != (unsigned int)myc) {
                const unsigned int key = h2k(u);
                kk[e] = (unsigned short)key;
                pp[e] = 0xFF80u;                        // -inf sentinel
                kneg++;
                atomicAdd(&s_hist[key >> 8], 1u);
            } else {
                kk[e] = 0u;
                if (j0 + e != i) {
                    pp[e] = (unsigned short)u;
                    pmax = fmaxf(pmax, h2f(u));
                } else {
                    pp[e] = 0xFF80u;
                }
            }
        }
        *(uint4*)(s_k  + j0) = *(uint4*)kk;
        *(uint4*)(s_pv + j0) = *(uint4*)pp;
    }
#pragma unroll
    for (int o = 16; o > 0; o >>= 1) {
        kneg += __shfl_xor_sync(0xFFFFFFFFu, kneg, o);
        pmax  = fmaxf(pmax, __shfl_xor_sync(0xFFFFFFFFu, pmax, o));
    }
    if (lane == 0) { s_wtot[wid] = (unsigned int)kneg; s_red[wid] = pmax; }
    __syncthreads();
    unsigned int K = 0; float pm = -1e30f;
#pragma unroll
    for (int w = 0; w < 8; w++) { K += s_wtot[w]; pm = fmaxf(pm, s_red[w]); }
    const int drop = max((int)floorf((float)K * 0.05f), 1);
    unsigned int r = (unsigned int)(drop + 1);

    auto select_bucket = [&](unsigned int rr) {
        const unsigned int h = s_hist[t];
        unsigned int suf = h;
#pragma unroll
        for (int o = 1; o < 32; o <<= 1) {
            const unsigned int w = __shfl_down_sync(0xFFFFFFFFu, suf, o);
            if (lane + o < 32) suf += w;
        }
        if (lane == 0) s_wtot[wid] = suf;
        __syncthreads();
#pragma unroll
        for (int w = 0; w < 8; w++) if (w > wid) suf += s_wtot[w];
        if (suf >= rr && (suf - h) < rr) {
            sh_sel = (unsigned int)t;
            sh_r   = rr - (suf - h);
            sh_h   = h;
        }
        __syncthreads();
    };

    // ---- round 0 (hist already built): top byte ----
    select_bucket(r);
    unsigned int prefix = sh_sel;
    r = sh_r;
    __syncthreads();

    // ---- round 1: low byte -> full 16-bit key ----
    s_hist[t] = 0;
    __syncthreads();
#pragma unroll
    for (int c = 0; c < 2; c++) {
        const int j0 = (c * NT + t) * 8;
        uint4 kw = *(const uint4*)(s_k + j0);
        unsigned int hw[4] = {kw.x, kw.y, kw.z, kw.w};
#pragma unroll
        for (int e = 0; e < 8; e++) {
            const unsigned int k = (hw[e >> 1] >> ((e & 1) * 16)) & 0xFFFFu;
            if ((k >> 8) == prefix)
                atomicAdd(&s_hist[k & 255u], 1u);
        }
    }
    __syncthreads();
    select_bucket(r);
    const unsigned int keyT = (prefix << 8) | sh_sel;   // full key of threshold
    const float T = k2f16(keyT);                        // == neg_thresh (bf16-exact)
    const int   m = (int)sh_h + 1 - (int)sh_r;          // kept negatives equal to T
    __syncthreads();

    // ---- fused final pass: pos_loss + neg_sum ----
    const float thr   = T + 0.1f;
    const float lower = fmaxf(0.6f, pm) - 0.1f;
    float ploss = 0.f, ns = 0.f;
#pragma unroll
    for (int c = 0; c < 2; c++) {
        const int j0 = (c * NT + t) * 8;
        uint4 kw = *(const uint4*)(s_k  + j0);
        uint4 pw = *(const uint4*)(s_pv + j0);
        unsigned int kh[4] = {kw.x, kw.y, kw.z, kw.w};
        unsigned int ph[4] = {pw.x, pw.y, pw.z, pw.w};
#pragma unroll
        for (int e = 0; e < 8; e++) {
            const unsigned int k  = (kh[e >> 1] >> ((e & 1) * 16)) & 0xFFFFu;
            const unsigned int pu = (ph[e >> 1] >> ((e & 1) * 16)) & 0xFFFFu;
            if (k) {
                const float v = k2f16(k);
                if (v < T && v > lower) ns += v;
            }
            if (pu != 0xFF80u) {
                const float v = h2f(pu);
                if (v < thr) ploss += 1.0f - v;
            }
        }
    }
#pragma unroll
    for (int o = 16; o > 0; o >>= 1) {
        ploss += __shfl_xor_sync(0xFFFFFFFFu, ploss, o);
        ns    += __shfl_xor_sync(0xFFFFFFFFu, ns, o);
    }
    if (lane == 0) { s_red[wid] = ploss; s_wtot[wid] = __float_as_uint(ns); }
    __syncthreads();

    if (t == 0) {
        float pl = 0.f, nss = 0.f;
#pragma unroll
        for (int w = 0; w < 8; w++) { pl += s_red[w]; nss += __uint_as_float(s_wtot[w]); }
        float loss = 0.f;
        if (pm > -1e29f) {                       // has_pos
            loss = pl + nss;
            if (T > lower) loss += (float)m * T; // ties at threshold (kept copies)
        }
        g_rowloss[i] = loss;
    }
}

// ---------------------------------------------------------------------------
__global__ void finalize_kernel(float* __restrict__ out) {
    __shared__ float s[1024];
    int t = threadIdx.x;
    float a = 0.f;
    for (int j = t; j < NROW; j += 1024) a += g_rowloss[j];
    s[t] = a; __syncthreads();
    for (int o = 512; o > 0; o >>= 1) { if (t < o) s[t] += s[t + o]; __syncthreads(); }
    if (t == 0) out[0] = s[0] / (float)NROW;
}

// ---------------------------------------------------------------------------
extern "C" void kernel_launch(void* const* d_in, const int* in_sizes, int n_in,
                              void* d_out, int out_size) {
    const float* emb   = (const float*)d_in[0];
    const int*   tgt32 = (const int*)d_in[1];
    float* out = (float*)d_out;

    cls_kernel<<<1, 1024>>>(tgt32);
    normalize_kernel<<<NROW, 256>>>(emb);
    gemm_kernel<<<528, 256>>>();
    row_loss_kernel<<<NROW, NT>>>();
    finalize_kernel<<<1, 1024>>>(out);
}

// round 15
// speedup vs baseline: 1.3084x; 1.0853x over previous
#include <cuda_runtime.h>
#include <cuda_bf16.h>
#include <stdint.h>

#define NROW 4096
#define DIM  1024
#define NT   256
#define RS   40          // padded smem row stride (bf16 elems) for conflict-free ldmatrix

// Static device scratch (no runtime allocation allowed).
__device__ __nv_bfloat16 g_Xb[(size_t)NROW * DIM];     // 8 MB normalized embeddings
__device__ __nv_bfloat16 g_SIMh[(size_t)NROW * NROW];  // 32 MB similarity matrix (bf16)
__device__ unsigned char g_cls[NROW];
__device__ float g_rowloss[NROW];

// Monotone bf16-bits <-> 16-bit key (ascending order preserved)
__device__ __forceinline__ unsigned int h2k(unsigned int u) {   // u = bf16 bits (16)
    return (u & 0x8000u) ? ((~u) & 0xFFFFu) : (u | 0x8000u);
}
__device__ __forceinline__ float k2f16(unsigned int k) {
    unsigned int u = (k & 0x8000u) ? (k & 0x7FFFu) : ((~k) & 0xFFFFu);
    return __uint_as_float(u << 16);
}
__device__ __forceinline__ float h2f(unsigned int u) {          // bf16 bits -> float
    return __uint_as_float(u << 16);
}

// ---------------------------------------------------------------------------
// Classes: reference declares int64 targets, but JAX without x64 emits int32.
__global__ __launch_bounds__(1024) void cls_kernel(const int* __restrict__ tgt32) {
    __shared__ int s_any;
    const int t = threadIdx.x;
    if (t == 0) s_any = 0;
    __syncthreads();
    int any = 0;
    for (int j = t; j < NROW / 2; j += 1024)
        any |= (tgt32[2 * j + 1] != 0);
    if (any) atomicOr(&s_any, 1);
    __syncthreads();
    const bool is64 = (s_any == 0);
    for (int i = t; i < NROW; i += 1024)
        g_cls[i] = (unsigned char)(is64 ? tgt32[2 * i] : tgt32[i]);
}

// ---------------------------------------------------------------------------
// Single-pass normalize: each thread owns one float4 of the row.
__global__ __launch_bounds__(256) void normalize_kernel(const float* __restrict__ emb) {
    const int i = blockIdx.x;
    const int t = threadIdx.x;
    const int lane = t & 31;
    const int wid  = t >> 5;
    __shared__ float s[8];

    float4 v = *(const float4*)(emb + (size_t)i * DIM + t * 4);
    float ss = v.x * v.x + v.y * v.y + v.z * v.z + v.w * v.w;
#pragma unroll
    for (int o = 16; o > 0; o >>= 1) ss += __shfl_xor_sync(0xFFFFFFFFu, ss, o);
    if (lane == 0) s[wid] = ss;
    __syncthreads();
    float tot = 0.f;
#pragma unroll
    for (int w = 0; w < 8; w++) tot += s[w];
    const float norm = fmaxf(sqrtf(tot), 1e-12f);

    unsigned int u0 = (unsigned int)__bfloat16_as_ushort(__float2bfloat16(v.x / norm));
    unsigned int u1 = (unsigned int)__bfloat16_as_ushort(__float2bfloat16(v.y / norm));
    unsigned int u2 = (unsigned int)__bfloat16_as_ushort(__float2bfloat16(v.z / norm));
    unsigned int u3 = (unsigned int)__bfloat16_as_ushort(__float2bfloat16(v.w / norm));
    uint2 pk;
    pk.x = u0 | (u1 << 16);
    pk.y = u2 | (u3 << 16);
    *(uint2*)(g_Xb + (size_t)i * DIM + t * 4) = pk;
}

// ---------------------------------------------------------------------------
// SIM = X * X^T in bf16 tensor cores (R8-proven mainloop). SYMMETRIC: 528
// lower-triangular 128x128 tiles; off-diagonal tiles also store their
// transpose via smem staging. OUTPUT IS bf16.
__device__ __forceinline__ void cp16(unsigned int smem_dst, const void* gsrc) {
    asm volatile("cp.async.cg.shared.global [%0], [%1], 16;\n" :: "r"(smem_dst), "l"(gsrc));
}
__device__ __forceinline__ void cp_commit() { asm volatile("cp.async.commit_group;\n"); }
__device__ __forceinline__ void cp_wait0() { asm volatile("cp.async.wait_group 0;\n"); }

__global__ __launch_bounds__(256) void gemm_kernel() {
    __shared__ __align__(16) char smbuf[2 * 128 * RS * 2 * 2];
    typedef __nv_bfloat16 Tile[128][RS];
    Tile* sA = reinterpret_cast<Tile*>(smbuf);
    Tile* sB = reinterpret_cast<Tile*>(smbuf + 2 * 128 * RS * 2);
    float (*tr)[132] = reinterpret_cast<float (*)[132]>(smbuf);

    const int t    = threadIdx.x;
    const int lane = t & 31;
    const int wid  = t >> 5;
    const int wm   = (wid >> 2) * 64;
    const int wn   = (wid & 3) * 32;

    const int b = blockIdx.x;
    int p = (int)((sqrtf(8.f * (float)b + 1.f) - 1.f) * 0.5f);
    while ((p + 1) * (p + 2) / 2 <= b) p++;
    while (p * (p + 1) / 2 > b) p--;
    const int q  = b - p * (p + 1) / 2;
    const int bi = p * 128;
    const int bj = q * 128;

    float acc[4][4][4];
#pragma unroll
    for (int mt = 0; mt < 4; mt++)
#pragma unroll
        for (int nt = 0; nt < 4; nt++)
#pragma unroll
            for (int r = 0; r < 4; r++) acc[mt][nt][r] = 0.f;

    auto load_stage = [&](int buf, int k0) {
#pragma unroll
        for (int c = t; c < 512; c += 256) {
            int row = c >> 2, off = (c & 3) * 8;
            cp16((unsigned int)__cvta_generic_to_shared(&sA[buf][row][off]),
                 g_Xb + (size_t)(bi + row) * DIM + k0 + off);
            cp16((unsigned int)__cvta_generic_to_shared(&sB[buf][row][off]),
                 g_Xb + (size_t)(bj + row) * DIM + k0 + off);
        }
    };

    load_stage(0, 0);
    cp_commit();
    cp_wait0();
    __syncthreads();

    for (int s = 0; s < DIM / 32; s++) {
        const int cbuf = s & 1;
        if (s + 1 < DIM / 32) {
            load_stage((s + 1) & 1, (s + 1) * 32);
            cp_commit();
        }
#pragma unroll
        for (int ks = 0; ks < 2; ks++) {
            unsigned int a[4][4], bb[4][2];
#pragma unroll
            for (int mt = 0; mt < 4; mt++) {
                unsigned int addr = (unsigned int)__cvta_generic_to_shared(
                    &sA[cbuf][wm + mt * 16 + (lane & 15)][ks * 16 + (lane >> 4) * 8]);
                asm volatile("ldmatrix.sync.aligned.m8n8.x4.shared.b16 {%0,%1,%2,%3}, [%4];"
                             : "=r"(a[mt][0]), "=r"(a[mt][1]), "=r"(a[mt][2]), "=r"(a[mt][3])
                             : "r"(addr));
            }
#pragma unroll
            for (int nt = 0; nt < 4; nt++) {
                unsigned int addr = (unsigned int)__cvta_generic_to_shared(
                    &sB[cbuf][wn + nt * 8 + (lane & 7)][ks * 16 + ((lane >> 3) & 1) * 8]);
                asm volatile("ldmatrix.sync.aligned.m8n8.x2.shared.b16 {%0,%1}, [%2];"
                             : "=r"(bb[nt][0]), "=r"(bb[nt][1]) : "r"(addr));
            }
#pragma unroll
            for (int mt = 0; mt < 4; mt++)
#pragma unroll
                for (int nt = 0; nt < 4; nt++) {
                    asm volatile(
                        "mma.sync.aligned.m16n8k16.row.col.f32.bf16.bf16.f32 "
                        "{%0,%1,%2,%3},{%4,%5,%6,%7},{%8,%9},{%0,%1,%2,%3};"
                        : "+f"(acc[mt][nt][0]), "+f"(acc[mt][nt][1]),
                          "+f"(acc[mt][nt][2]), "+f"(acc[mt][nt][3])
                        : "r"(a[mt][0]), "r"(a[mt][1]), "r"(a[mt][2]), "r"(a[mt][3]),
                          "r"(bb[nt][0]), "r"(bb[nt][1]));
                }
        }
        if (s + 1 < DIM / 32) cp_wait0();
        __syncthreads();
    }

    // ---- direct store of (bi, bj) tile (bf16, coalesced) ----
#pragma unroll
    for (int mt = 0; mt < 4; mt++) {
#pragma unroll
        for (int nt = 0; nt < 4; nt++) {
            int r0 = bi + wm + mt * 16 + (lane >> 2);
            int c0 = bj + wn + nt * 8 + (lane & 3) * 2;
            __nv_bfloat162 p01 = __floats2bfloat162_rn(acc[mt][nt][0], acc[mt][nt][1]);
            __nv_bfloat162 p23 = __floats2bfloat162_rn(acc[mt][nt][2], acc[mt][nt][3]);
            *(__nv_bfloat162*)(g_SIMh + (size_t)r0 * NROW + c0) = p01;
            *(__nv_bfloat162*)(g_SIMh + (size_t)(r0 + 8) * NROW + c0) = p23;
        }
    }

    // ---- transposed store of (bj, bi) tile, staged via smem ----
    if (p != q) {
        for (int cc = 0; cc < 4; cc++) {
            __syncthreads();
            if ((wid & 3) == cc) {
#pragma unroll
                for (int mt = 0; mt < 4; mt++)
#pragma unroll
                    for (int nt = 0; nt < 4; nt++) {
                        int r0 = wm + mt * 16 + (lane >> 2);
                        int c0 = nt * 8 + (lane & 3) * 2;
                        tr[c0    ][r0    ] = acc[mt][nt][0];
                        tr[c0 + 1][r0    ] = acc[mt][nt][1];
                        tr[c0    ][r0 + 8] = acc[mt][nt][2];
                        tr[c0 + 1][r0 + 8] = acc[mt][nt][3];
                    }
            }
            __syncthreads();
            const int c = t >> 3;
            const int r = (t & 7) * 16;
            __nv_bfloat16* dst = g_SIMh + (size_t)(bj + cc * 32 + c) * NROW + bi + r;
#pragma unroll
            for (int k = 0; k < 4; k++) {
                float4 f = *(float4*)(&tr[c][r + k * 4]);
                __nv_bfloat162 lo = __floats2bfloat162_rn(f.x, f.y);
                __nv_bfloat162 hi = __floats2bfloat162_rn(f.z, f.w);
                uint2 w;
                w.x = *(unsigned int*)&lo;
                w.y = *(unsigned int*)&hi;
                *(uint2*)(dst + k * 4) = w;
            }
        }
    }
}

// ---------------------------------------------------------------------------
// Per-row loss on the bf16 SIM. 16-bit keys -> exact 2-round radix select.
// Positives COMPACTED into a list (sparse: ~N/256 per row); negative-sum scan
// gated on T > lower (unsatisfiable otherwise).
__global__ __launch_bounds__(NT) void row_loss_kernel() {
    __shared__ __align__(16) unsigned short s_k[NROW];    // 8 KB: neg keys (0 = not neg)
    __shared__ __align__(16) unsigned short s_pos[NROW];  // 8 KB: compact positive bf16 bits
    __shared__ unsigned int s_hist[256];
    __shared__ unsigned int s_wtot[8];
    __shared__ float        s_red[8];
    __shared__ unsigned int sh_sel, sh_r, sh_h, sh_pcnt;

    const int i    = blockIdx.x;
    const int t    = threadIdx.x;
    const int lane = t & 31;
    const int wid  = t >> 5;
    const unsigned char myc = g_cls[i];
    const __nv_bfloat16* row = g_SIMh + (size_t)i * NROW;

    s_hist[t] = 0;
    if (t == 0) sh_pcnt = 0;
    __syncthreads();

    // ---- load pass: neg keys + pos compaction + round-0 hist + K + pos_max ----
    float pmax = -1e30f;
    int   kneg = 0;
#pragma unroll
    for (int c = 0; c < 2; c++) {
        const int j0 = (c * NT + t) * 8;
        uint4 kv = *(const uint4*)(row + j0);          // 8 bf16
        uint2 cw = *(const uint2*)(g_cls + j0);        // 8 classes
        unsigned int hw[4] = {kv.x, kv.y, kv.z, kv.w};
        unsigned short kk[8];
#pragma unroll
        for (int e = 0; e < 8; e++) {
            const unsigned int u  = (hw[e >> 1] >> ((e & 1) * 16)) & 0xFFFFu;
            const unsigned int cl = ((e < 4 ? cw.x : cw.y) >> ((e & 3) * 8)) & 0xFFu;
            if (cl != (unsigned int)myc) {
                const unsigned int key = h2k(u);
                kk[e] = (unsigned short)key;
                kneg++;
                atomicAdd(&s_hist[key >> 8], 1u);
            } else {
                kk[e] = 0u;
                if (j0 + e != i) {
                    const unsigned int slot = atomicAdd(&sh_pcnt, 1u);
                    s_pos[slot] = (unsigned short)u;
                    pmax = fmaxf(pmax, h2f(u));
                }
            }
        }
        *(uint4*)(s_k + j0) = *(uint4*)kk;
    }
#pragma unroll
    for (int o = 16; o > 0; o >>= 1) {
        kneg += __shfl_xor_sync(0xFFFFFFFFu, kneg, o);
        pmax  = fmaxf(pmax, __shfl_xor_sync(0xFFFFFFFFu, pmax, o));
    }
    if (lane == 0) { s_wtot[wid] = (unsigned int)kneg; s_red[wid] = pmax; }
    __syncthreads();
    unsigned int K = 0; float pm = -1e30f;
#pragma unroll
    for (int w = 0; w < 8; w++) { K += s_wtot[w]; pm = fmaxf(pm, s_red[w]); }
    const int drop = max((int)floorf((float)K * 0.05f), 1);
    unsigned int r = (unsigned int)(drop + 1);
    const unsigned int pcnt = sh_pcnt;

    auto select_bucket = [&](unsigned int rr) {
        const unsigned int h = s_hist[t];
        unsigned int suf = h;
#pragma unroll
        for (int o = 1; o < 32; o <<= 1) {
            const unsigned int w = __shfl_down_sync(0xFFFFFFFFu, suf, o);
            if (lane + o < 32) suf += w;
        }
        if (lane == 0) s_wtot[wid] = suf;
        __syncthreads();
#pragma unroll
        for (int w = 0; w < 8; w++) if (w > wid) suf += s_wtot[w];
        if (suf >= rr && (suf - h) < rr) {
            sh_sel = (unsigned int)t;
            sh_r   = rr - (suf - h);
            sh_h   = h;
        }
        __syncthreads();
    };

    // ---- round 0 (hist already built): top byte ----
    select_bucket(r);
    unsigned int prefix = sh_sel;
    r = sh_r;
    __syncthreads();

    // ---- round 1: low byte -> full 16-bit key ----
    s_hist[t] = 0;
    __syncthreads();
#pragma unroll
    for (int c = 0; c < 2; c++) {
        const int j0 = (c * NT + t) * 8;
        uint4 kw = *(const uint4*)(s_k + j0);
        unsigned int hw[4] = {kw.x, kw.y, kw.z, kw.w};
#pragma unroll
        for (int e = 0; e < 8; e++) {
            const unsigned int k = (hw[e >> 1] >> ((e & 1) * 16)) & 0xFFFFu;
            if ((k >> 8) == prefix)
                atomicAdd(&s_hist[k & 255u], 1u);
        }
    }
    __syncthreads();
    select_bucket(r);
    const unsigned int keyT = (prefix << 8) | sh_sel;   // full key of threshold
    const float T = k2f16(keyT);                        // == neg_thresh (bf16-exact)
    const int   m = (int)sh_h + 1 - (int)sh_r;          // kept negatives equal to T
    __syncthreads();

    // ---- final: pos_loss over compact list; neg scan only if satisfiable ----
    const float thr   = T + 0.1f;
    const float lower = fmaxf(0.6f, pm) - 0.1f;
    float ploss = 0.f, ns = 0.f;

    for (unsigned int j = t; j < pcnt; j += NT) {
        const float v = h2f((unsigned int)s_pos[j]);
        if (v < thr) ploss += 1.0f - v;
    }

    if (T > lower) {
#pragma unroll
        for (int c = 0; c < 2; c++) {
            const int j0 = (c * NT + t) * 8;
            uint4 kw = *(const uint4*)(s_k + j0);
            unsigned int hw[4] = {kw.x, kw.y, kw.z, kw.w};
#pragma unroll
            for (int e = 0; e < 8; e++) {
                const unsigned int k = (hw[e >> 1] >> ((e & 1) * 16)) & 0xFFFFu;
                if (k) {
                    const float v = k2f16(k);
                    if (v < T && v > lower) ns += v;
                }
            }
        }
    }

#pragma unroll
    for (int o = 16; o > 0; o >>= 1) {
        ploss += __shfl_xor_sync(0xFFFFFFFFu, ploss, o);
        ns    += __shfl_xor_sync(0xFFFFFFFFu, ns, o);
    }
    if (lane == 0) { s_red[wid] = ploss; s_wtot[wid] = __float_as_uint(ns); }
    __syncthreads();

    if (t == 0) {
        float pl = 0.f, nss = 0.f;
#pragma unroll
        for (int w = 0; w < 8; w++) { pl += s_red[w]; nss += __uint_as_float(s_wtot[w]); }
        float loss = 0.f;
        if (pm > -1e29f) {                       // has_pos
            loss = pl + nss;
            if (T > lower) loss += (float)m * T; // ties at threshold (kept copies)
        }
        g_rowloss[i] = loss;
    }
}

// ---------------------------------------------------------------------------
__global__ void finalize_kernel(float* __restrict__ out) {
    __shared__ float s[1024];
    int t = threadIdx.x;
    float a = 0.f;
    for (int j = t; j < NROW; j += 1024) a += g_rowloss[j];
    s[t] = a; __syncthreads();
    for (int o = 512; o > 0; o >>= 1) { if (t < o) s[t] += s[t + o]; __syncthreads(); }
    if (t == 0) out[0] = s[0] / (float)NROW;
}

// ---------------------------------------------------------------------------
extern "C" void kernel_launch(void* const* d_in, const int* in_sizes, int n_in,
                              void* d_out, int out_size) {
    const float* emb   = (const float*)d_in[0];
    const int*   tgt32 = (const int*)d_in[1];
    float* out = (float*)d_out;

    cls_kernel<<<1, 1024>>>(tgt32);
    normalize_kernel<<<NROW, 256>>>(emb);
    gemm_kernel<<<528, 256>>>();
    row_loss_kernel<<<NROW, NT>>>();
    finalize_kernel<<<1, 1024>>>(out);
}